// round 11
// baseline (speedup 1.0000x reference)
#include <cuda_runtime.h>
#include <math.h>

// ---- problem constants ----
#define BB 16
#define MM 256
#define NN 512
#define H1 16
#define H2 8
#define UU 8
#define OUTC 4

typedef unsigned long long ull;

// ---- packed f32x2 helpers (SASS FFMA2 path, PTX-only) ----
__device__ __forceinline__ ull fma2(ull a, ull b, ull c) {
    ull d; asm("fma.rn.f32x2 %0,%1,%2,%3;" : "=l"(d) : "l"(a), "l"(b), "l"(c)); return d;
}
__device__ __forceinline__ ull add2(ull a, ull b) {
    ull d; asm("add.rn.f32x2 %0,%1,%2;" : "=l"(d) : "l"(a), "l"(b)); return d;
}
__device__ __forceinline__ ull pack2(float lo, float hi) {
    ull d; asm("mov.b64 %0,{%1,%2};" : "=l"(d) : "f"(lo), "f"(hi)); return d;
}
__device__ __forceinline__ ull dup2(float v) { return pack2(v, v); }
__device__ __forceinline__ float2 unp2(ull a) {
    float2 f; asm("mov.b64 {%0,%1},%2;" : "=f"(f.x), "=f"(f.y) : "l"(a)); return f;
}
__device__ __forceinline__ ull relu2(ull a) {
    float2 f = unp2(a);
    return pack2(fmaxf(f.x, 0.f), fmaxf(f.y, 0.f));
}

// ---- scratch (device globals; no allocs allowed) ----
__device__ float g_G[BB * NN * NN];       // Gram matrices  [B,N,N]
__device__ float g_u[BB * NN * UU];       // node state u   [B,N,U]
__device__ float g_h[BB * NN * H1];       // GRU hidden     [B*N,H1]
__device__ float g_P[BB * NN * H1];       // layer1 self part + sigma + bias
__device__ float g_Q[BB * NN * H1];       // layer1 neighbor part
__device__ float g_msum[BB * NN * UU];    // message sums   [B,N,U]

// ---- shared helper: P/Q from u (caller provides w_p1 rows in shared) ----
// P[k] = W1[k,0:8]·u + W1[k,17]*sig + b1[k] ;  Q[k] = W1[k,8:16]·u
__device__ __forceinline__ void compute_PQ(const float* __restrict__ W1s,  // [16][18]
                                           const float* __restrict__ B1s,  // [16]
                                           const float* u8, float sg, int idx) {
#pragma unroll
    for (int k = 0; k < H1; k++) {
        const float* wr = W1s + k * 18;
        float pv = fmaf(wr[17], sg, B1s[k]);
        float qv = 0.f;
#pragma unroll
        for (int i = 0; i < UU; i++) {
            pv = fmaf(wr[i], u8[i], pv);
            qv = fmaf(wr[8 + i], u8[i], qv);
        }
        g_P[(size_t)idx * H1 + k] = pv;
        g_Q[(size_t)idx * H1 + k] = qv;
    }
}

// ---- shared helper: GRU cell body. Reads g_msum/g_h, returns gnew and
// u8 = W_up gnew + b_up in registers. ----
__device__ __forceinline__ void gru_body(int idx, int b, int n,
                                         const float* __restrict__ rin,
                                         const float* __restrict__ Sin,
                                         const float* __restrict__ Wih,
                                         const float* __restrict__ Bih,
                                         const float* __restrict__ Whh,
                                         const float* __restrict__ Bhh,
                                         const float* __restrict__ Wup,
                                         const float* __restrict__ Bup,
                                         float* gnew, float* u8) {
    float gin[10];
#pragma unroll
    for (int i = 0; i < UU; i++) gin[i] = g_msum[(size_t)idx * UU + i];
    gin[8] = rin[b * NN + n];
    gin[9] = Sin[b * NN + n];

    float hv[H1];
#pragma unroll
    for (int i = 0; i < H1; i++) hv[i] = g_h[(size_t)idx * H1 + i];

    float rr[H1], zz[H1];
#pragma unroll
    for (int h = 0; h < H1; h++) {
        float a = Bih[h];
#pragma unroll
        for (int i = 0; i < 10; i++) a = fmaf(Wih[h * 10 + i], gin[i], a);
        float c = Bhh[h];
#pragma unroll
        for (int i = 0; i < H1; i++) c = fmaf(Whh[h * H1 + i], hv[i], c);
        rr[h] = 1.f / (1.f + expf(-(a + c)));
    }
#pragma unroll
    for (int h = 0; h < H1; h++) {
        float a = Bih[16 + h];
#pragma unroll
        for (int i = 0; i < 10; i++) a = fmaf(Wih[(16 + h) * 10 + i], gin[i], a);
        float c = Bhh[16 + h];
#pragma unroll
        for (int i = 0; i < H1; i++) c = fmaf(Whh[(16 + h) * H1 + i], hv[i], c);
        zz[h] = 1.f / (1.f + expf(-(a + c)));
    }
#pragma unroll
    for (int h = 0; h < H1; h++) {
        float a = Bih[32 + h];
#pragma unroll
        for (int i = 0; i < 10; i++) a = fmaf(Wih[(32 + h) * 10 + i], gin[i], a);
        float c = Bhh[32 + h];
#pragma unroll
        for (int i = 0; i < H1; i++) c = fmaf(Whh[(32 + h) * H1 + i], hv[i], c);
        float nn = tanhf(fmaf(rr[h], c, a));
        gnew[h] = fmaf(1.f - zz[h], nn, zz[h] * hv[h]);
    }

#pragma unroll
    for (int o = 0; o < UU; o++) {
        float u = Bup[o];
#pragma unroll
        for (int i = 0; i < H1; i++) u = fmaf(Wup[o * H1 + i], gnew[i], u);
        u8[o] = u;
    }
}

// ============================================================
// Kernel 1: G = A^T A per batch, symmetric tiles (36 of 64)
// f32x2-packed 4x4 microtile (A staged duplicated)
// ============================================================
__global__ __launch_bounds__(256) void k_gram(const float* __restrict__ A) {
    int b = blockIdx.y;
    int p = blockIdx.x;                 // 0..35  upper-triangular tile pair
    int it = 0, acc = 0;
    while (p >= acc + (8 - it)) { acc += 8 - it; it++; }
    int jt = it + (p - acc);
    int i0 = it * 64, j0 = jt * 64;

    __shared__ __align__(16) float As2[16][128];   // duplicated pairs
    __shared__ __align__(16) float Bs[16][64];

    int t  = threadIdx.x;
    int tx = t & 15, ty = t >> 4;
    const float* Ab = A + (size_t)b * MM * NN;

    ull acc2[4][2];
#pragma unroll
    for (int r = 0; r < 4; r++) { acc2[r][0] = 0ull; acc2[r][1] = 0ull; }

    int l  = t * 4;
    int lk = l >> 6, li = l & 63;

    for (int k0 = 0; k0 < MM; k0 += 16) {
        float4 av = *reinterpret_cast<const float4*>(&Ab[(k0 + lk) * NN + i0 + li]);
        float4 bv = *reinterpret_cast<const float4*>(&Ab[(k0 + lk) * NN + j0 + li]);
        *reinterpret_cast<float4*>(&As2[lk][li * 2])     = make_float4(av.x, av.x, av.y, av.y);
        *reinterpret_cast<float4*>(&As2[lk][li * 2 + 4]) = make_float4(av.z, av.z, av.w, av.w);
        *reinterpret_cast<float4*>(&Bs[lk][li]) = bv;
        __syncthreads();
#pragma unroll
        for (int kk = 0; kk < 16; kk++) {
            const ulonglong2* ap = reinterpret_cast<const ulonglong2*>(&As2[kk][ty * 8]);
            ulonglong2 a01 = ap[0], a23 = ap[1];
            ulonglong2 bq = *reinterpret_cast<const ulonglong2*>(&Bs[kk][tx * 4]);
            ull a2[4] = {a01.x, a01.y, a23.x, a23.y};
#pragma unroll
            for (int r = 0; r < 4; r++) {
                acc2[r][0] = fma2(a2[r], bq.x, acc2[r][0]);
                acc2[r][1] = fma2(a2[r], bq.y, acc2[r][1]);
            }
        }
        __syncthreads();
    }

    float* Gb = g_G + (size_t)b * NN * NN;
#pragma unroll
    for (int r = 0; r < 4; r++) {
        int gi = i0 + ty * 4 + r;
#pragma unroll
        for (int cp = 0; cp < 2; cp++) {
            float2 v = unp2(acc2[r][cp]);
            int gj = j0 + tx * 4 + cp * 2;
            Gb[gi * NN + gj]     = v.x;
            Gb[gi * NN + gj + 1] = v.y;
            if (it != jt) {
                Gb[gj * NN + gi]       = v.x;
                Gb[(gj + 1) * NN + gi] = v.y;
            }
        }
    }
}

// ============================================================
// Kernel 2 (fused): ATy, diag(G), u0; zero GRU hidden; P/Q for layer 0
// grid: (N/256, B), 256 threads
// ============================================================
__global__ __launch_bounds__(256) void k_init(const float* __restrict__ A,
                                              const float* __restrict__ y,
                                              const float* __restrict__ sigma2,
                                              const float* __restrict__ w_init,
                                              const float* __restrict__ b_init,
                                              const float* __restrict__ w_p1,
                                              const float* __restrict__ b_p1) {
    int b = blockIdx.y;
    int n = blockIdx.x * 256 + threadIdx.x;
    __shared__ float ys[MM];
    __shared__ float W1s[H1 * 18], B1s[H1];
    int t = threadIdx.x;
    ys[t] = y[b * MM + t];                  // blockDim==256==MM
    // FIX (R4): H1*18 = 288 > 256 threads -> must be a strided loop.
    for (int i = t; i < H1 * 18; i += 256) W1s[i] = w_p1[i];
    if (t < H1) B1s[t] = b_p1[t];
    __syncthreads();

    const float* Ab = A + (size_t)b * MM * NN;
    float aty = 0.f;
#pragma unroll 4
    for (int m = 0; m < MM; m++) aty = fmaf(Ab[m * NN + n], ys[m], aty);

    float dg = g_G[(size_t)b * NN * NN + n * (NN + 1)];
    float sg = sigma2[b];

    int idx = b * NN + n;
    float u8[UU];
#pragma unroll
    for (int o = 0; o < UU; o++) {
        u8[o] = fmaf(w_init[o * 3 + 0], aty,
                fmaf(w_init[o * 3 + 1], dg,
                fmaf(w_init[o * 3 + 2], sg, b_init[o])));
        g_u[(size_t)idx * UU + o] = u8[o];
    }
#pragma unroll
    for (int o = 0; o < H1; o++) g_h[(size_t)idx * H1 + o] = 0.f;

    compute_PQ(W1s, B1s, u8, sg, idx);
}

// ============================================================
// Kernel 3: edge MLP + message sum, f32x2-packed (edge pair j, j+256).
// One warp per destination node n, 4 warps/block (128 threads).
// Qs2 holds pre-interleaved pairs: Qs2[j][2k]=Q[j][k], [2k+1]=Q[j+256][k].
// Rows padded to 36 floats -> conflict-free LDS.128 (8-lane phases).
// Weights staged in shared pre-duplicated as u64 pairs.
// G row front-batched into registers (16 LDGs up front).
// ============================================================
__global__ __launch_bounds__(128) void k_edge(const float* __restrict__ w_p1,
                                              const float* __restrict__ w_p2,
                                              const float* __restrict__ b_p2,
                                              const float* __restrict__ w_p3,
                                              const float* __restrict__ b_p3) {
    int b  = blockIdx.x >> 7;                 // 128 blocks per batch
    int n0 = (blockIdx.x & 127) * 4;

    __shared__ __align__(16) float Qs2[NN / 2][36];
    __shared__ ull W2d[H2 * H1];
    __shared__ ull W3d[UU * H2];
    __shared__ ull b2d[H2], b3d[UU];

    int t = threadIdx.x;

    // stage Q[b] interleaved: j<256 -> even slots, j>=256 -> odd slots
    for (int i = t; i < NN * 4; i += 128) {
        int j = i >> 2, c = (i & 3) * 4;
        float4 v = *reinterpret_cast<const float4*>(&g_Q[((size_t)b * NN + j) * H1 + c]);
        int jp = j & 255, par = j >> 8;
        Qs2[jp][2 * c + par]       = v.x;
        Qs2[jp][2 * (c + 1) + par] = v.y;
        Qs2[jp][2 * (c + 2) + par] = v.z;
        Qs2[jp][2 * (c + 3) + par] = v.w;
    }
    if (t < H2 * H1) W2d[t] = dup2(w_p2[t]);
    if (t < UU * H2) W3d[t] = dup2(w_p3[t]);
    if (t < H2) b2d[t] = dup2(b_p2[t]);
    if (t < UU) b3d[t] = dup2(b_p3[t]);
    __syncthreads();

    int warp = t >> 5, lane = t & 31;
    int n = n0 + warp;
    int idx = b * NN + n;

    // front-batch the full G row slice for this lane (16 independent LDGs)
    const float* Grow = g_G + ((size_t)b * NN + n) * NN;
    float Glo[8], Ghi[8];
#pragma unroll
    for (int itn = 0; itn < 8; itn++) {
        Glo[itn] = Grow[lane + itn * 32];
        Ghi[itn] = Grow[lane + itn * 32 + 256];
    }

    // per-n constants, duplicated into both packed halves
    ull pp[H1], wgp[H1];
    {
        const float4* Pp = reinterpret_cast<const float4*>(&g_P[(size_t)idx * H1]);
#pragma unroll
        for (int q4 = 0; q4 < 4; q4++) {
            float4 pv = Pp[q4];
            pp[q4 * 4 + 0] = dup2(pv.x);
            pp[q4 * 4 + 1] = dup2(pv.y);
            pp[q4 * 4 + 2] = dup2(pv.z);
            pp[q4 * 4 + 3] = dup2(pv.w);
        }
    }
#pragma unroll
    for (int k = 0; k < H1; k++) wgp[k] = dup2(w_p1[k * 18 + 16]);

    ull macc[UU];
#pragma unroll
    for (int o = 0; o < UU; o++) macc[o] = 0ull;

    for (int itn = 0; itn < 8; itn++) {
        int jp = lane + itn * 32;                 // pair handles (jp, jp+256)
        ull Gp = pack2(Glo[itn], Ghi[itn]);
        ull maskp = pack2(jp != n ? 1.f : 0.f, (jp + 256) != n ? 1.f : 0.f);

        // load 16 packed q pairs (8 LDS.128)
        ull qp[H1];
        {
            const ulonglong2* qr = reinterpret_cast<const ulonglong2*>(&Qs2[jp][0]);
#pragma unroll
            for (int m = 0; m < 8; m++) {
                ulonglong2 v = qr[m];
                qp[2 * m]     = v.x;
                qp[2 * m + 1] = v.y;
            }
        }

        ull h1p[H1];
#pragma unroll
        for (int k = 0; k < H1; k++)
            h1p[k] = relu2(add2(fma2(wgp[k], Gp, qp[k]), pp[k]));

        ull h2p[H2];
#pragma unroll
        for (int o = 0; o < H2; o++) {
            ull a = b2d[o];
#pragma unroll
            for (int i = 0; i < H1; i++) a = fma2(W2d[o * H1 + i], h1p[i], a);
            h2p[o] = relu2(a);
        }

#pragma unroll
        for (int o = 0; o < UU; o++) {
            ull m = b3d[o];
#pragma unroll
            for (int i = 0; i < H2; i++) m = fma2(W3d[o * H2 + i], h2p[i], m);
            macc[o] = fma2(m, maskp, macc[o]);
        }
    }

#pragma unroll
    for (int o = 0; o < UU; o++) {
        float2 f = unp2(macc[o]);
        float v = f.x + f.y;
#pragma unroll
        for (int s = 16; s > 0; s >>= 1) v += __shfl_xor_sync(0xFFFFFFFFu, v, s);
        if (lane == 0) g_msum[(size_t)idx * UU + o] = v;
    }
}

// ============================================================
// Kernel 4a (mid layer): GRU + u = W_up g + b_up + P/Q for next layer
// ============================================================
__global__ __launch_bounds__(128) void k_gru_mid(const float* __restrict__ rin,
                                                 const float* __restrict__ Sin,
                                                 const float* __restrict__ sigma2,
                                                 const float* __restrict__ w_ih,
                                                 const float* __restrict__ b_ih,
                                                 const float* __restrict__ w_hh,
                                                 const float* __restrict__ b_hh,
                                                 const float* __restrict__ w_up,
                                                 const float* __restrict__ b_up,
                                                 const float* __restrict__ w_p1,
                                                 const float* __restrict__ b_p1) {
    __shared__ float Wih[48 * 10], Bih[48], Whh[48 * 16], Bhh[48], Wup[UU * H1], Bup[UU];
    __shared__ float W1s[H1 * 18], B1s[H1];
    int t = threadIdx.x;
    for (int i = t; i < 480; i += 128) Wih[i] = w_ih[i];
    for (int i = t; i < 768; i += 128) Whh[i] = w_hh[i];
    for (int i = t; i < H1 * 18; i += 128) W1s[i] = w_p1[i];
    if (t < 48) { Bih[t] = b_ih[t]; Bhh[t] = b_hh[t]; }
    if (t < UU * H1) Wup[t] = w_up[t];
    if (t < UU) Bup[t] = b_up[t];
    if (t < H1) B1s[t] = b_p1[t];
    __syncthreads();

    int idx = blockIdx.x * 128 + t;         // B*N threads
    int b = idx >> 9, n = idx & 511;

    float gnew[H1], u8[UU];
    gru_body(idx, b, n, rin, Sin, Wih, Bih, Whh, Bhh, Wup, Bup, gnew, u8);

#pragma unroll
    for (int h = 0; h < H1; h++) g_h[(size_t)idx * H1 + h] = gnew[h];

    compute_PQ(W1s, B1s, u8, sigma2[b], idx);
}

// ============================================================
// Kernel 4b (final layer, fused readout): GRU + u + readout MLP + softmax
// Writes probs | u | g directly to out; no scratch writes.
// ============================================================
__global__ __launch_bounds__(128) void k_gru_final(const float* __restrict__ rin,
                                                   const float* __restrict__ Sin,
                                                   const float* __restrict__ w_ih,
                                                   const float* __restrict__ b_ih,
                                                   const float* __restrict__ w_hh,
                                                   const float* __restrict__ b_hh,
                                                   const float* __restrict__ w_up,
                                                   const float* __restrict__ b_up,
                                                   const float* __restrict__ w_r1,
                                                   const float* __restrict__ b_r1,
                                                   const float* __restrict__ w_r2,
                                                   const float* __restrict__ b_r2,
                                                   const float* __restrict__ w_r3,
                                                   const float* __restrict__ b_r3,
                                                   float* __restrict__ out) {
    __shared__ float Wih[48 * 10], Bih[48], Whh[48 * 16], Bhh[48], Wup[UU * H1], Bup[UU];
    __shared__ float W1r[H1 * UU], B1r[H1], W2r[H2 * H1], B2r[H2], W3r[OUTC * H2], B3r[OUTC];
    int t = threadIdx.x;
    for (int i = t; i < 480; i += 128) Wih[i] = w_ih[i];
    for (int i = t; i < 768; i += 128) Whh[i] = w_hh[i];
    if (t < 48) { Bih[t] = b_ih[t]; Bhh[t] = b_hh[t]; }
    if (t < UU * H1) Wup[t] = w_up[t];
    if (t < UU) Bup[t] = b_up[t];
    if (t < H1 * UU) W1r[t] = w_r1[t];
    if (t < H1) B1r[t] = b_r1[t];
    if (t < H2 * H1) W2r[t] = w_r2[t];
    if (t < H2) B2r[t] = b_r2[t];
    if (t < OUTC * H2) W3r[t] = w_r3[t];
    if (t < OUTC) B3r[t] = b_r3[t];
    __syncthreads();

    int idx = blockIdx.x * 128 + t;         // B*N threads
    int b = idx >> 9, n = idx & 511;

    float gnew[H1], u8[UU];
    gru_body(idx, b, n, rin, Sin, Wih, Bih, Whh, Bhh, Wup, Bup, gnew, u8);

    // readout MLP
    float h1[H1];
#pragma unroll
    for (int k = 0; k < H1; k++) {
        float a = B1r[k];
#pragma unroll
        for (int i = 0; i < UU; i++) a = fmaf(W1r[k * UU + i], u8[i], a);
        h1[k] = fmaxf(a, 0.f);
    }
    float h2[H2];
#pragma unroll
    for (int o = 0; o < H2; o++) {
        float a = B2r[o];
#pragma unroll
        for (int i = 0; i < H1; i++) a = fmaf(W2r[o * H1 + i], h1[i], a);
        h2[o] = fmaxf(a, 0.f);
    }
    float lg[OUTC];
    float mx = -1e30f;
#pragma unroll
    for (int o = 0; o < OUTC; o++) {
        float a = B3r[o];
#pragma unroll
        for (int i = 0; i < H2; i++) a = fmaf(W3r[o * H2 + i], h2[i], a);
        lg[o] = a;
        mx = fmaxf(mx, a);
    }
    float s = 0.f;
#pragma unroll
    for (int o = 0; o < OUTC; o++) { lg[o] = expf(lg[o] - mx); s += lg[o]; }
    float inv = 1.f / s;

    // outputs: probs [B,N,4] | u [B,N,8] | g [B*N,16]
#pragma unroll
    for (int o = 0; o < OUTC; o++) out[(size_t)idx * OUTC + o] = lg[o] * inv;
    float* ou = out + (size_t)BB * NN * OUTC;
#pragma unroll
    for (int o = 0; o < UU; o++) ou[(size_t)idx * UU + o] = u8[o];
    float* og = out + (size_t)BB * NN * (OUTC + UU);
#pragma unroll
    for (int o = 0; o < H1; o++) og[(size_t)idx * H1 + o] = gnew[o];
}

// ============================================================
extern "C" void kernel_launch(void* const* d_in, const int* in_sizes, int n_in,
                              void* d_out, int out_size) {
    const float* y      = (const float*)d_in[0];
    const float* A      = (const float*)d_in[1];
    const float* sigma2 = (const float*)d_in[2];
    const float* r      = (const float*)d_in[3];
    const float* Sigma  = (const float*)d_in[4];
    const float* w_init = (const float*)d_in[5];
    const float* b_init = (const float*)d_in[6];
    const float* w_p1   = (const float*)d_in[7];
    const float* b_p1   = (const float*)d_in[8];
    const float* w_p2   = (const float*)d_in[9];
    const float* b_p2   = (const float*)d_in[10];
    const float* w_p3   = (const float*)d_in[11];
    const float* b_p3   = (const float*)d_in[12];
    const float* w_ih   = (const float*)d_in[13];
    const float* b_ih   = (const float*)d_in[14];
    const float* w_hh   = (const float*)d_in[15];
    const float* b_hh   = (const float*)d_in[16];
    const float* w_up   = (const float*)d_in[17];
    const float* b_up   = (const float*)d_in[18];
    const float* w_r1   = (const float*)d_in[19];
    const float* b_r1   = (const float*)d_in[20];
    const float* w_r2   = (const float*)d_in[21];
    const float* b_r2   = (const float*)d_in[22];
    const float* w_r3   = (const float*)d_in[23];
    const float* b_r3   = (const float*)d_in[24];
    float* out = (float*)d_out;

    k_gram<<<dim3(36, BB), 256>>>(A);
    k_init<<<dim3(NN / 256, BB), 256>>>(A, y, sigma2, w_init, b_init, w_p1, b_p1);

    // layer 0
    k_edge<<<BB * NN / 4, 128>>>(w_p1, w_p2, b_p2, w_p3, b_p3);
    k_gru_mid<<<BB * NN / 128, 128>>>(r, Sigma, sigma2, w_ih, b_ih, w_hh, b_hh,
                                      w_up, b_up, w_p1, b_p1);
    // layer 1 (final) + fused readout
    k_edge<<<BB * NN / 4, 128>>>(w_p1, w_p2, b_p2, w_p3, b_p3);
    k_gru_final<<<BB * NN / 128, 128>>>(r, Sigma, w_ih, b_ih, w_hh, b_hh,
                                        w_up, b_up, w_r1, b_r1, w_r2, b_r2,
                                        w_r3, b_r3, out);
}

// round 15
// speedup vs baseline: 1.9972x; 1.9972x over previous
#include <cuda_runtime.h>
#include <math.h>

// ---- problem constants ----
#define BB 16
#define MM 256
#define NN 512
#define H1 16
#define H2 8
#define UU 8
#define OUTC 4

// ---- scratch (device globals; no allocs allowed) ----
__device__ float g_G[BB * NN * NN];          // Gram matrices  [B,N,N]
__device__ float g_h[BB * NN * H1];          // GRU hidden     [B*N,H1]
__device__ float g_P[2][BB * NN * H1];       // layer1 self part (double-buffered by layer)
__device__ float g_Q[2][BB * NN * H1];       // layer1 neighbor part (double-buffered)

// ============================================================
// Kernel 1: G = A^T A per batch, symmetric tiles (36 of 64)
// scalar 4x4 microtile, 64x64 tile, BK=16
// ============================================================
__global__ __launch_bounds__(256) void k_gram(const float* __restrict__ A) {
    int b = blockIdx.y;
    int p = blockIdx.x;                 // 0..35  upper-triangular tile pair
    int it = 0, acc = 0;
    while (p >= acc + (8 - it)) { acc += 8 - it; it++; }
    int jt = it + (p - acc);
    int i0 = it * 64, j0 = jt * 64;

    __shared__ __align__(16) float As[16][64];
    __shared__ __align__(16) float Bs[16][64];

    int t  = threadIdx.x;
    int tx = t & 15, ty = t >> 4;
    const float* Ab = A + (size_t)b * MM * NN;

    float accv[4][4];
#pragma unroll
    for (int r = 0; r < 4; r++)
#pragma unroll
        for (int c = 0; c < 4; c++) accv[r][c] = 0.f;

    int l  = t * 4;
    int lk = l >> 6, li = l & 63;

    for (int k0 = 0; k0 < MM; k0 += 16) {
        *reinterpret_cast<float4*>(&As[lk][li]) =
            *reinterpret_cast<const float4*>(&Ab[(k0 + lk) * NN + i0 + li]);
        *reinterpret_cast<float4*>(&Bs[lk][li]) =
            *reinterpret_cast<const float4*>(&Ab[(k0 + lk) * NN + j0 + li]);
        __syncthreads();
#pragma unroll
        for (int kk = 0; kk < 16; kk++) {
            float4 av = *reinterpret_cast<float4*>(&As[kk][ty * 4]);
            float4 bv = *reinterpret_cast<float4*>(&Bs[kk][tx * 4]);
            float a4[4] = {av.x, av.y, av.z, av.w};
            float b4[4] = {bv.x, bv.y, bv.z, bv.w};
#pragma unroll
            for (int r = 0; r < 4; r++)
#pragma unroll
                for (int c = 0; c < 4; c++)
                    accv[r][c] = fmaf(a4[r], b4[c], accv[r][c]);
        }
        __syncthreads();
    }

    float* Gb = g_G + (size_t)b * NN * NN;
#pragma unroll
    for (int r = 0; r < 4; r++) {
        int gi = i0 + ty * 4 + r;
#pragma unroll
        for (int c = 0; c < 4; c++) {
            int gj = j0 + tx * 4 + c;
            Gb[gi * NN + gj] = accv[r][c];
            if (it != jt) Gb[gj * NN + gi] = accv[r][c];
        }
    }
}

// ============================================================
// Kernel 2: ATy, diag(G), u0 (in regs); zero GRU hidden; P/Q -> buffer 0
// ============================================================
__global__ __launch_bounds__(256) void k_init(const float* __restrict__ A,
                                              const float* __restrict__ y,
                                              const float* __restrict__ sigma2,
                                              const float* __restrict__ w_init,
                                              const float* __restrict__ b_init,
                                              const float* __restrict__ w_p1,
                                              const float* __restrict__ b_p1) {
    int b = blockIdx.y;
    int n = blockIdx.x * 256 + threadIdx.x;
    __shared__ float ys[MM];
    __shared__ float W1s[H1 * 18], B1s[H1];
    int t = threadIdx.x;
    ys[t] = y[b * MM + t];                  // blockDim==256==MM
    for (int i = t; i < H1 * 18; i += 256) W1s[i] = w_p1[i];   // 288 > 256: strided
    if (t < H1) B1s[t] = b_p1[t];
    __syncthreads();

    const float* Ab = A + (size_t)b * MM * NN;
    float aty = 0.f;
#pragma unroll 4
    for (int m = 0; m < MM; m++) aty = fmaf(Ab[m * NN + n], ys[m], aty);

    float dg = g_G[(size_t)b * NN * NN + n * (NN + 1)];
    float sg = sigma2[b];

    int idx = b * NN + n;
    float u8[UU];
#pragma unroll
    for (int o = 0; o < UU; o++) {
        u8[o] = fmaf(w_init[o * 3 + 0], aty,
                fmaf(w_init[o * 3 + 1], dg,
                fmaf(w_init[o * 3 + 2], sg, b_init[o])));
    }
#pragma unroll
    for (int o = 0; o < H1; o++) g_h[(size_t)idx * H1 + o] = 0.f;

#pragma unroll
    for (int k = 0; k < H1; k++) {
        const float* wr = W1s + k * 18;
        float pv = fmaf(wr[17], sg, B1s[k]);
        float qv = 0.f;
#pragma unroll
        for (int i = 0; i < UU; i++) {
            pv = fmaf(wr[i], u8[i], pv);
            qv = fmaf(wr[8 + i], u8[i], qv);
        }
        g_P[0][(size_t)idx * H1 + k] = pv;
        g_Q[0][(size_t)idx * H1 + k] = qv;
    }
}

// ============================================================
// Kernel 3 (fused): edge MLP + message sum + GRU + (P/Q next layer | readout)
// Warp per destination node n, 4 warps/block, lane per source j (16 iters).
// Qs rows padded to 20 floats -> conflict-free LDS.128 (bank stride 20%32).
// FINAL=0: writes g_h and P/Q buffer pr^1.  FINAL=1: writes probs|u|g to out.
// ============================================================
template <int FINAL>
__global__ __launch_bounds__(128) void k_edge_t(
    const float* __restrict__ w_p1,
    const float* __restrict__ w_p2, const float* __restrict__ b_p2,
    const float* __restrict__ w_p3, const float* __restrict__ b_p3,
    const float* __restrict__ rin,  const float* __restrict__ Sin,
    const float* __restrict__ sigma2,
    const float* __restrict__ w_ih, const float* __restrict__ b_ih,
    const float* __restrict__ w_hh, const float* __restrict__ b_hh,
    const float* __restrict__ w_up, const float* __restrict__ b_up,
    const float* __restrict__ b_p1,
    const float* __restrict__ w_r1, const float* __restrict__ b_r1,
    const float* __restrict__ w_r2, const float* __restrict__ b_r2,
    const float* __restrict__ w_r3, const float* __restrict__ b_r3,
    float* __restrict__ out, int pr)
{
    __shared__ __align__(16) float Qs[NN][20];             // 40960 B
    __shared__ float W2s[H2 * H1], b2s[H2], W3s[UU * H2], b3s[UU];
    __shared__ float Wih[48 * 10], Whh[48 * 16], Wup[UU * H1];
    __shared__ float Xs[316];   // union: mid -> W1s[288]+B1s[16]; final -> readout weights
    __shared__ float scr[4][24]; // per-warp: gnew[16] | u8[8]  (reused in readout)

    int b  = blockIdx.x >> 7;
    int n0 = (blockIdx.x & 127) * 4;
    int t  = threadIdx.x;
    int bn0 = b * NN;

    // ---- stage Q[b] (from buffer pr) ----
    const float* Qbuf = g_Q[pr];
    for (int i = t; i < NN * 4; i += 128) {
        int j = i >> 2, c = (i & 3) * 4;
        float4 v = *reinterpret_cast<const float4*>(&Qbuf[((size_t)(bn0 + j)) * H1 + c]);
        *reinterpret_cast<float4*>(&Qs[j][c]) = v;
    }
    for (int i = t; i < H2 * H1; i += 128) W2s[i] = w_p2[i];
    if (t < H2) b2s[t] = b_p2[t];
    if (t < UU * H2) W3s[t] = w_p3[t];
    if (t < UU) b3s[t] = b_p3[t];
    for (int i = t; i < 480; i += 128) Wih[i] = w_ih[i];
    for (int i = t; i < 768; i += 128) Whh[i] = w_hh[i];
    for (int i = t; i < UU * H1; i += 128) Wup[i] = w_up[i];
    if (FINAL) {
        for (int i = t; i < H1 * UU; i += 128) Xs[i] = w_r1[i];          // 0..127
        if (t < H1) Xs[128 + t] = b_r1[t];                               // 128..143
        for (int i = t; i < H2 * H1; i += 128) Xs[144 + i] = w_r2[i];    // 144..271
        if (t < H2) Xs[272 + t] = b_r2[t];                               // 272..279
        if (t < OUTC * H2) Xs[280 + t] = w_r3[t];                        // 280..311
        if (t < OUTC) Xs[312 + t] = b_r3[t];                             // 312..315
    } else {
        for (int i = t; i < H1 * 18; i += 128) Xs[i] = w_p1[i];          // 0..287
        if (t < H1) Xs[288 + t] = b_p1[t];                               // 288..303
    }
    __syncthreads();

    int warp = t >> 5, lane = t & 31;
    int n = n0 + warp;
    int idx = bn0 + n;

    // ---- per-n constants (broadcast LDGs) ----
    float p[H1], wg[H1];
    {
        const float* Pb = &g_P[pr][(size_t)idx * H1];
#pragma unroll
        for (int k = 0; k < H1; k++) p[k] = Pb[k];
    }
#pragma unroll
    for (int k = 0; k < H1; k++) wg[k] = w_p1[k * 18 + 16];

    // front-batch the G row slice for this lane (16 independent LDGs)
    const float* Grow = g_G + (size_t)idx * NN;
    float Gv[16];
#pragma unroll
    for (int it = 0; it < 16; it++) Gv[it] = Grow[lane + it * 32];

    float macc[UU];
#pragma unroll
    for (int o = 0; o < UU; o++) macc[o] = 0.f;

    for (int it = 0; it < 16; it++) {
        int j = lane + it * 32;

        float4 q0 = *reinterpret_cast<const float4*>(&Qs[j][0]);
        float4 q1 = *reinterpret_cast<const float4*>(&Qs[j][4]);
        float4 q2 = *reinterpret_cast<const float4*>(&Qs[j][8]);
        float4 q3 = *reinterpret_cast<const float4*>(&Qs[j][12]);
        float qa[H1] = {q0.x,q0.y,q0.z,q0.w, q1.x,q1.y,q1.z,q1.w,
                        q2.x,q2.y,q2.z,q2.w, q3.x,q3.y,q3.z,q3.w};

        float h1[H1];
#pragma unroll
        for (int k = 0; k < H1; k++)
            h1[k] = fmaxf(fmaf(wg[k], Gv[it], p[k] + qa[k]), 0.f);

        float h2[H2];
#pragma unroll
        for (int o = 0; o < H2; o++) {
            float a = b2s[o];
#pragma unroll
            for (int i = 0; i < H1; i++) a = fmaf(W2s[o * H1 + i], h1[i], a);
            h2[o] = fmaxf(a, 0.f);
        }

        float mask = (j != n) ? 1.f : 0.f;
#pragma unroll
        for (int o = 0; o < UU; o++) {
            float m = b3s[o];
#pragma unroll
            for (int i = 0; i < H2; i++) m = fmaf(W3s[o * H2 + i], h2[i], m);
            macc[o] = fmaf(m, mask, macc[o]);
        }
    }

    // reduce: afterwards ALL lanes hold the full message sums
#pragma unroll
    for (int o = 0; o < UU; o++) {
        float v = macc[o];
#pragma unroll
        for (int s = 16; s > 0; s >>= 1) v += __shfl_xor_sync(0xFFFFFFFFu, v, s);
        macc[o] = v;
    }

    // ======== fused GRU epilogue (warp-cooperative) ========
    float gin8 = rin[idx];
    float gin9 = Sin[idx];

    float hv[H1];
#pragma unroll
    for (int i = 0; i < H1; i++) hv[i] = g_h[(size_t)idx * H1 + i];

    if (lane < H1) {
        int h = lane;
        // r gate
        float a = b_ih[h], c = b_hh[h];
#pragma unroll
        for (int i = 0; i < UU; i++) a = fmaf(Wih[h * 10 + i], macc[i], a);
        a = fmaf(Wih[h * 10 + 8], gin8, a);
        a = fmaf(Wih[h * 10 + 9], gin9, a);
#pragma unroll
        for (int i = 0; i < H1; i++) c = fmaf(Whh[h * H1 + i], hv[i], c);
        float rr = 1.f / (1.f + expf(-(a + c)));
        // z gate
        a = b_ih[16 + h]; c = b_hh[16 + h];
#pragma unroll
        for (int i = 0; i < UU; i++) a = fmaf(Wih[(16 + h) * 10 + i], macc[i], a);
        a = fmaf(Wih[(16 + h) * 10 + 8], gin8, a);
        a = fmaf(Wih[(16 + h) * 10 + 9], gin9, a);
#pragma unroll
        for (int i = 0; i < H1; i++) c = fmaf(Whh[(16 + h) * H1 + i], hv[i], c);
        float zz = 1.f / (1.f + expf(-(a + c)));
        // n gate
        a = b_ih[32 + h]; c = b_hh[32 + h];
#pragma unroll
        for (int i = 0; i < UU; i++) a = fmaf(Wih[(32 + h) * 10 + i], macc[i], a);
        a = fmaf(Wih[(32 + h) * 10 + 8], gin8, a);
        a = fmaf(Wih[(32 + h) * 10 + 9], gin9, a);
#pragma unroll
        for (int i = 0; i < H1; i++) c = fmaf(Whh[(32 + h) * H1 + i], hv[i], c);
        float nn = tanhf(fmaf(rr, c, a));
        float gnew = fmaf(1.f - zz, nn, zz * hv[h]);
        scr[warp][h] = gnew;
        if (!FINAL) g_h[(size_t)idx * H1 + h] = gnew;
        else {
            float* og = out + (size_t)BB * NN * (OUTC + UU);
            og[(size_t)idx * H1 + h] = gnew;
        }
    }
    __syncwarp();

    // u8 = W_up gnew + b_up
    if (lane < UU) {
        float u = b_up[lane];
#pragma unroll
        for (int i = 0; i < H1; i++) u = fmaf(Wup[lane * H1 + i], scr[warp][i], u);
        scr[warp][16 + lane] = u;
        if (FINAL) {
            float* ou = out + (size_t)BB * NN * OUTC;
            ou[(size_t)idx * UU + lane] = u;
        }
    }
    __syncwarp();

    if (!FINAL) {
        // P/Q for next layer -> buffer pr^1
        if (lane < H1) {
            int k = lane;
            float sg = sigma2[b];
            float pv = fmaf(Xs[k * 18 + 17], sg, Xs[288 + k]);
            float qv = 0.f;
#pragma unroll
            for (int i = 0; i < UU; i++) {
                pv = fmaf(Xs[k * 18 + i],     scr[warp][16 + i], pv);
                qv = fmaf(Xs[k * 18 + 8 + i], scr[warp][16 + i], qv);
            }
            g_P[pr ^ 1][(size_t)idx * H1 + k] = pv;
            g_Q[pr ^ 1][(size_t)idx * H1 + k] = qv;
        }
    } else {
        // readout MLP + softmax
        float h1r = 0.f;
        if (lane < H1) {
            float a = Xs[128 + lane];
#pragma unroll
            for (int i = 0; i < UU; i++) a = fmaf(Xs[lane * UU + i], scr[warp][16 + i], a);
            h1r = fmaxf(a, 0.f);
        }
        __syncwarp();
        if (lane < H1) scr[warp][lane] = h1r;   // overwrite gnew (already output)
        __syncwarp();
        if (lane < H2) {
            float a = Xs[272 + lane];
#pragma unroll
            for (int i = 0; i < H1; i++) a = fmaf(Xs[144 + lane * H1 + i], scr[warp][i], a);
            scr[warp][16 + lane] = fmaxf(a, 0.f);   // overwrite u8 (already output)
        }
        __syncwarp();
        float lgv = -1e30f;
        if (lane < OUTC) {
            float a = Xs[312 + lane];
#pragma unroll
            for (int i = 0; i < H2; i++) a = fmaf(Xs[280 + lane * H2 + i], scr[warp][16 + i], a);
            lgv = a;
        }
        // softmax within lane groups of 4 (lanes >= 4 hold -inf / 0)
        float m1 = fmaxf(lgv, __shfl_xor_sync(0xFFFFFFFFu, lgv, 1));
        float mx = fmaxf(m1,  __shfl_xor_sync(0xFFFFFFFFu, m1, 2));
        float ev = (lane < OUTC) ? expf(lgv - mx) : 0.f;
        float s1 = ev + __shfl_xor_sync(0xFFFFFFFFu, ev, 1);
        float ss = s1 + __shfl_xor_sync(0xFFFFFFFFu, s1, 2);
        if (lane < OUTC) out[(size_t)idx * OUTC + lane] = ev / ss;
    }
}

// ============================================================
extern "C" void kernel_launch(void* const* d_in, const int* in_sizes, int n_in,
                              void* d_out, int out_size) {
    const float* y      = (const float*)d_in[0];
    const float* A      = (const float*)d_in[1];
    const float* sigma2 = (const float*)d_in[2];
    const float* r      = (const float*)d_in[3];
    const float* Sigma  = (const float*)d_in[4];
    const float* w_init = (const float*)d_in[5];
    const float* b_init = (const float*)d_in[6];
    const float* w_p1   = (const float*)d_in[7];
    const float* b_p1   = (const float*)d_in[8];
    const float* w_p2   = (const float*)d_in[9];
    const float* b_p2   = (const float*)d_in[10];
    const float* w_p3   = (const float*)d_in[11];
    const float* b_p3   = (const float*)d_in[12];
    const float* w_ih   = (const float*)d_in[13];
    const float* b_ih   = (const float*)d_in[14];
    const float* w_hh   = (const float*)d_in[15];
    const float* b_hh   = (const float*)d_in[16];
    const float* w_up   = (const float*)d_in[17];
    const float* b_up   = (const float*)d_in[18];
    const float* w_r1   = (const float*)d_in[19];
    const float* b_r1   = (const float*)d_in[20];
    const float* w_r2   = (const float*)d_in[21];
    const float* b_r2   = (const float*)d_in[22];
    const float* w_r3   = (const float*)d_in[23];
    const float* b_r3   = (const float*)d_in[24];
    float* out = (float*)d_out;

    k_gram<<<dim3(36, BB), 256>>>(A);
    k_init<<<dim3(NN / 256, BB), 256>>>(A, y, sigma2, w_init, b_init, w_p1, b_p1);

    // layer 0: edge MLP + GRU + P/Q(buf1)
    k_edge_t<0><<<BB * 128, 128>>>(w_p1, w_p2, b_p2, w_p3, b_p3, r, Sigma, sigma2,
                                   w_ih, b_ih, w_hh, b_hh, w_up, b_up, b_p1,
                                   w_r1, b_r1, w_r2, b_r2, w_r3, b_r3, out, 0);
    // layer 1: edge MLP + GRU + readout -> out
    k_edge_t<1><<<BB * 128, 128>>>(w_p1, w_p2, b_p2, w_p3, b_p3, r, Sigma, sigma2,
                                   w_ih, b_ih, w_hh, b_hh, w_up, b_up, b_p1,
                                   w_r1, b_r1, w_r2, b_r2, w_r3, b_r3, out, 1);
}